// round 1
// baseline (speedup 1.0000x reference)
#include <cuda_runtime.h>

typedef unsigned long long ull;

#define HID   256
#define NCOL  49152                    // OC*IC*KW = 128*128*3
#define NPDE  1024
#define W2D_ELEMS 37748736ULL          // 2048*2048*3*3

// ---- scratch (allocation-free rule: __device__ globals) ----
__device__ float g_part[16 * 64];      // partial sums for pde mean
__device__ float g_pf[HID];            // pde_feat + b1
__device__ float g_hidT[HID * 256];    // hidden transposed: [hid][r]

// ---- f32x2 helpers (FFMA2 path: ptxas never auto-fuses this) ----
__device__ __forceinline__ ull pack2(float lo, float hi) {
    ull r; asm("mov.b64 %0,{%1,%2};" : "=l"(r) : "f"(lo), "f"(hi)); return r;
}
__device__ __forceinline__ ull ffma2(ull a, ull b, ull c) {
    ull d; asm("fma.rn.f32x2 %0,%1,%2,%3;" : "=l"(d) : "l"(a), "l"(b), "l"(c)); return d;
}
__device__ __forceinline__ float2 unpack2(ull v) {
    float2 f; asm("mov.b64 {%0,%1},%2;" : "=f"(f.x), "=f"(f.y) : "l"(v)); return f;
}

// ---- Stage 1a: partial column sums of pde_inputs (16 blocks) ----
__global__ void k_mean(const float* __restrict__ pde) {
    __shared__ float sm[256];
    int b = blockIdx.x;                 // 0..15, each handles 64 rows
    int t = threadIdx.x;
    int d = t & 63, sl = t >> 6;
    float s = 0.f;
    int n0 = b * 64;
    #pragma unroll
    for (int it = 0; it < 16; ++it) {
        int n = n0 + sl + it * 4;
        s += pde[n * 64 + d];
    }
    sm[t] = s;
    __syncthreads();
    if (t < 64)
        g_part[b * 64 + t] = sm[t] + sm[t + 64] + sm[t + 128] + sm[t + 192];
}

// ---- Stage 1b: pde_feat = mean @ U1 + b1 ; also writes bb tail of output ----
__global__ void k_prep(const float* __restrict__ U1, const float* __restrict__ b1,
                       const float* __restrict__ z_bias, const float* __restrict__ u_bias,
                       float* __restrict__ out) {
    __shared__ float mean[64];
    int t = threadIdx.x;
    if (t < 64) {
        float s = 0.f;
        #pragma unroll
        for (int b = 0; b < 16; ++b) s += g_part[b * 64 + t];
        mean[t] = s * (1.0f / 1024.0f);
    }
    __syncthreads();
    float acc = b1[t];
    #pragma unroll 8
    for (int d = 0; d < 64; ++d) acc += mean[d] * U1[d * 256 + t];
    g_pf[t] = acc;
    // bb = z_bias + unet_1d_bias, appended after w_2d
    #pragma unroll
    for (int e = 0; e < 8; ++e) {
        int o = e * 256 + t;
        out[W2D_ELEMS + o] = z_bias[o] + u_bias[o];
    }
}

// ---- Stage 2: hidden = tanh(Z @ W1 + pf), stored TRANSPOSED [hid][r] ----
__global__ void k_hidden(const float* __restrict__ Z, const float* __restrict__ W1) {
    __shared__ float zs[64];
    int r = blockIdx.x, t = threadIdx.x;
    if (t < 64) zs[t] = Z[r * 64 + t];
    __syncthreads();
    float acc = g_pf[t];
    #pragma unroll 8
    for (int d = 0; d < 64; ++d) acc += zs[d] * W1[d * 256 + t];
    g_hidT[t * 256 + r] = tanhf(acc);
}

// ---- Stage 3: fused GEMM (hidden @ W2 + b2) * unet -> w_2d ----
// C[r, c]: r = h*16+kc (256 rows), c = (oc*128+ic)*3+kw (49152 cols)
// Block tile: 32 rows x 128 pairs (384 cols). Thread: 8 rows x 2 adjacent pairs x 3 kw.
// f32x2 lanes carry the 2 adjacent pairs; A values are broadcast-packed.
__global__ __launch_bounds__(256) void k_main(const float* __restrict__ W2,
                                              const float* __restrict__ b2,
                                              const float* __restrict__ unet,
                                              float* __restrict__ out) {
    __shared__ __align__(16) float As[16][32];       // [kk][row]  (2 KB)
    __shared__ __align__(16) float Bs[16][3][132];   // [kk][kw][pair], pad 132 (~25 KB)

    int tid = threadIdx.x;
    int tx = tid & 63;          // pair-pair index (2 pairs each)
    int ty = tid >> 6;          // row group (8 rows each)
    int rt = blockIdx.x;        // 0..7   row tile
    int pt = blockIdx.y;        // 0..127 pair tile (== oc)
    int R0 = rt * 32;
    int C0 = pt * 384;

    ull acc[8][3];
    #pragma unroll
    for (int j = 0; j < 8; ++j)
        #pragma unroll
        for (int kw = 0; kw < 3; ++kw) acc[j][kw] = 0ULL;

    for (int k0 = 0; k0 < HID; k0 += 16) {
        // --- fill As: 512 elems (coalesced from transposed hidden, conflict-free STS)
        {
            int idx = tid;
            #pragma unroll
            for (int it = 0; it < 2; ++it, idx += 256) {
                int kk = idx >> 5, rr = idx & 31;
                As[kk][rr] = g_hidT[(k0 + kk) * 256 + R0 + rr];
            }
        }
        // --- fill Bs: 6144 elems (coalesced LDG; planar kw layout, pad kills STS conflicts)
        {
            #pragma unroll
            for (int it = 0; it < 24; ++it) {
                int idx = it * 256 + tid;
                int kk  = idx / 384;
                int rem = idx - kk * 384;
                int pp  = rem / 3;
                int kw  = rem - pp * 3;
                Bs[kk][kw][pp] = W2[(size_t)(k0 + kk) * NCOL + C0 + rem];
            }
        }
        __syncthreads();

        #pragma unroll
        for (int kk = 0; kk < 16; ++kk) {
            float4 av0 = *reinterpret_cast<const float4*>(&As[kk][ty * 8]);
            float4 av1 = *reinterpret_cast<const float4*>(&As[kk][ty * 8 + 4]);
            ull b0  = *reinterpret_cast<const ull*>(&Bs[kk][0][tx * 2]);
            ull b1v = *reinterpret_cast<const ull*>(&Bs[kk][1][tx * 2]);
            ull b2v = *reinterpret_cast<const ull*>(&Bs[kk][2][tx * 2]);
            ull a_[8];
            a_[0] = pack2(av0.x, av0.x); a_[1] = pack2(av0.y, av0.y);
            a_[2] = pack2(av0.z, av0.z); a_[3] = pack2(av0.w, av0.w);
            a_[4] = pack2(av1.x, av1.x); a_[5] = pack2(av1.y, av1.y);
            a_[6] = pack2(av1.z, av1.z); a_[7] = pack2(av1.w, av1.w);
            #pragma unroll
            for (int j = 0; j < 8; ++j) {
                acc[j][0] = ffma2(a_[j], b0,  acc[j][0]);
                acc[j][1] = ffma2(a_[j], b1v, acc[j][1]);
                acc[j][2] = ffma2(a_[j], b2v, acc[j][2]);
            }
        }
        __syncthreads();
    }

    // --- fused epilogue: exe = C + b2; out[o,i,k,l] = exe[k] * unet[o,i,l]
    int p0 = (pt << 7) + 2 * tx;                     // pair index (even)
    const float2* b2p = reinterpret_cast<const float2*>(b2 + (size_t)p0 * 3);
    float2 q0 = b2p[0], q1 = b2p[1], q2 = b2p[2];
    float b2a[6] = { q0.x, q0.y, q1.x,   q1.y, q2.x, q2.y };

    #pragma unroll
    for (int j = 0; j < 8; ++j) {
        int r  = R0 + ty * 8 + j;
        int o  = ((r >> 4) << 7) + pt;               // h*128 + oc
        int i0 = ((r & 15) << 7) + 2 * tx;           // kc*128 + ic (even)
        size_t base = (size_t)o * 2048 + i0;
        const float2* up = reinterpret_cast<const float2*>(unet + base * 3);
        float2 u0 = up[0], u1 = up[1], u2 = up[2];
        float ua[6] = { u0.x, u0.y, u1.x,   u1.y, u2.x, u2.y };
        float w[18];
        #pragma unroll
        for (int kw = 0; kw < 3; ++kw) {
            float2 v = unpack2(acc[j][kw]);
            float e0 = v.x + b2a[kw];                // pair p0
            float e1 = v.y + b2a[3 + kw];            // pair p0+1
            w[kw * 3 + 0] = e0 * ua[0];
            w[kw * 3 + 1] = e0 * ua[1];
            w[kw * 3 + 2] = e0 * ua[2];
            w[9 + kw * 3 + 0] = e1 * ua[3];
            w[9 + kw * 3 + 1] = e1 * ua[4];
            w[9 + kw * 3 + 2] = e1 * ua[5];
        }
        float2* dst = reinterpret_cast<float2*>(out + base * 9);
        #pragma unroll
        for (int q = 0; q < 9; ++q) dst[q] = make_float2(w[2 * q], w[2 * q + 1]);
    }
}

extern "C" void kernel_launch(void* const* d_in, const int* in_sizes, int n_in,
                              void* d_out, int out_size) {
    const float* Z      = (const float*)d_in[0];
    const float* z_bias = (const float*)d_in[1];
    const float* unet_w = (const float*)d_in[2];
    const float* unet_b = (const float*)d_in[3];
    const float* pde    = (const float*)d_in[4];
    const float* W1     = (const float*)d_in[5];
    const float* U1     = (const float*)d_in[6];
    const float* b1     = (const float*)d_in[7];
    const float* W2     = (const float*)d_in[8];
    const float* b2     = (const float*)d_in[9];
    float* out = (float*)d_out;

    k_mean<<<16, 256>>>(pde);
    k_prep<<<1, 256>>>(U1, b1, z_bias, unet_b, out);
    k_hidden<<<256, 256>>>(Z, W1);
    k_main<<<dim3(8, 128), 256>>>(W2, b2, unet_w, out);
}

// round 2
// speedup vs baseline: 1.0520x; 1.0520x over previous
#include <cuda_runtime.h>

typedef unsigned long long ull;

#define HID   256
#define NCOL  49152                    // OC*IC*KW = 128*128*3
#define W2D_ELEMS 37748736ULL          // 2048*2048*3*3

// ---- scratch (allocation-free rule: __device__ globals) ----
__device__ float  g_part[16 * 64];         // partial sums for pde mean
__device__ float  g_pf[HID];               // pde_feat + b1
__device__ float2 g_dup[HID * 256];        // hidden, transposed AND duplicated: [hid][r] = {h,h}

// ---- f32x2 helpers ----
__device__ __forceinline__ ull ffma2(ull a, ull b, ull c) {
    ull d; asm("fma.rn.f32x2 %0,%1,%2,%3;" : "=l"(d) : "l"(a), "l"(b), "l"(c)); return d;
}
__device__ __forceinline__ float2 unpack2(ull v) {
    float2 f; asm("mov.b64 {%0,%1},%2;" : "=f"(f.x), "=f"(f.y) : "l"(v)); return f;
}
__device__ __forceinline__ void cp16(void* dst_smem, const void* src_gmem) {
    unsigned u = (unsigned)__cvta_generic_to_shared(dst_smem);
    asm volatile("cp.async.cg.shared.global [%0],[%1],16;" :: "r"(u), "l"(src_gmem));
}
#define CP_COMMIT() asm volatile("cp.async.commit_group;")
#define CP_WAIT1()  asm volatile("cp.async.wait_group 1;")

// ---- Stage 1a: partial column sums of pde_inputs (16 blocks) ----
__global__ void k_mean(const float* __restrict__ pde) {
    __shared__ float sm[256];
    int b = blockIdx.x;
    int t = threadIdx.x;
    int d = t & 63, sl = t >> 6;
    float s = 0.f;
    int n0 = b * 64;
    #pragma unroll
    for (int it = 0; it < 16; ++it) {
        int n = n0 + sl + it * 4;
        s += pde[n * 64 + d];
    }
    sm[t] = s;
    __syncthreads();
    if (t < 64)
        g_part[b * 64 + t] = sm[t] + sm[t + 64] + sm[t + 128] + sm[t + 192];
}

// ---- Stage 1b: pde_feat = mean @ U1 + b1 ; bb tail of output ----
__global__ void k_prep(const float* __restrict__ U1, const float* __restrict__ b1,
                       const float* __restrict__ z_bias, const float* __restrict__ u_bias,
                       float* __restrict__ out) {
    __shared__ float mean[64];
    int t = threadIdx.x;
    if (t < 64) {
        float s = 0.f;
        #pragma unroll
        for (int b = 0; b < 16; ++b) s += g_part[b * 64 + t];
        mean[t] = s * (1.0f / 1024.0f);
    }
    __syncthreads();
    float acc = b1[t];
    #pragma unroll 8
    for (int d = 0; d < 64; ++d) acc += mean[d] * U1[d * 256 + t];
    g_pf[t] = acc;
    #pragma unroll
    for (int e = 0; e < 8; ++e) {
        int o = e * 256 + t;
        out[W2D_ELEMS + o] = z_bias[o] + u_bias[o];
    }
}

// ---- Stage 2: hidden = tanh(Z @ W1 + pf), stored transposed + duplicated ----
__global__ void k_hidden(const float* __restrict__ Z, const float* __restrict__ W1) {
    __shared__ float zs[64];
    int r = blockIdx.x, t = threadIdx.x;
    if (t < 64) zs[t] = Z[r * 64 + t];
    __syncthreads();
    float acc = g_pf[t];
    #pragma unroll 8
    for (int d = 0; d < 64; ++d) acc += zs[d] * W1[d * 256 + t];
    float h = tanhf(acc);
    g_dup[t * 256 + r] = make_float2(h, h);
}

// ---- Stage 3: fused GEMM (hidden @ W2 + b2) * unet -> w_2d ----
// Block: 32 rows x 384 raw cols. Thread: 8 rows x 6 consecutive raw cols
// (= 2 (oc,ic)-pairs x 3 kw), f32x2 lanes over adjacent raw columns.
// 3-stage cp.async pipeline, one barrier per k-chunk.
#define BROW 388                        // 384 + 4 pad floats (16B multiple)
#define BSTAGE (16 * BROW)              // floats per B stage

__global__ __launch_bounds__(256, 2) void k_main(const float* __restrict__ W2,
                                                 const float* __restrict__ b2,
                                                 const float* __restrict__ unet,
                                                 float* __restrict__ out) {
    extern __shared__ char smem_raw[];
    float*  Bs = (float*)smem_raw;                         // 3 * 24832 B
    float2* As = (float2*)(smem_raw + 3 * BSTAGE * 4);     // 3 * 16 * 32 * 8 B

    int tid = threadIdx.x;
    int tx = tid & 63;              // 6 raw cols each
    int ty = tid >> 6;              // 8 rows each
    int rt = blockIdx.x;            // 0..7   row tile (fastest: rt blocks share W2 stripe in L2)
    int pt = blockIdx.y;            // 0..127 col tile
    int R0 = rt * 32;
    size_t C0 = (size_t)pt * 384;

    ull acc[8][3];
    #pragma unroll
    for (int j = 0; j < 8; ++j)
        #pragma unroll
        for (int q = 0; q < 3; ++q) acc[j][q] = 0ULL;

    auto load_chunk = [&](int i, int st) {
        const float* gB = W2 + (size_t)(i * 16) * NCOL + C0;
        float* sB = Bs + st * BSTAGE;
        #pragma unroll
        for (int it = 0; it < 6; ++it) {
            int idx = it * 256 + tid;       // 0..1535 float4s
            int kk  = idx / 96;             // 96 float4 per row
            int c4  = idx - kk * 96;
            cp16(sB + kk * BROW + c4 * 4, gB + (size_t)kk * NCOL + c4 * 4);
        }
        int kk = tid >> 4, v = tid & 15;    // 16 x 16B per A stage
        cp16(&As[(st * 16 + kk) * 32 + v * 2],
             &g_dup[(i * 16 + kk) * 256 + R0 + v * 2]);
    };

    auto compute = [&](int st) {
        const float*  sB = Bs + st * BSTAGE;
        const float2* sA = As + st * 16 * 32 + ty * 8;
        #pragma unroll
        for (int kk = 0; kk < 16; ++kk) {
            const ull* arow = (const ull*)(sA + kk * 32);
            const float* brow = sB + kk * BROW + 6 * tx;
            ull b0  = *(const ull*)(brow);
            ull b1v = *(const ull*)(brow + 2);
            ull b2v = *(const ull*)(brow + 4);
            #pragma unroll
            for (int j = 0; j < 8; ++j) {
                ull a = arow[j];
                acc[j][0] = ffma2(a, b0,  acc[j][0]);
                acc[j][1] = ffma2(a, b1v, acc[j][1]);
                acc[j][2] = ffma2(a, b2v, acc[j][2]);
            }
        }
    };

    load_chunk(0, 0); CP_COMMIT();
    load_chunk(1, 1); CP_COMMIT();
    #pragma unroll 1
    for (int i = 0; i < 16; ++i) {
        CP_WAIT1();                 // own copies of chunk i done (always-commit keeps count uniform)
        __syncthreads();            // all warps: chunk i visible, compute(i-1) finished
        if (i + 2 < 16) load_chunk(i + 2, (i + 2) % 3);
        CP_COMMIT();                // commit every iter (possibly empty group)
        compute(i % 3);
    }

    // --- fused epilogue: exe = C + b2; out[o,i,kq,l] = exe[kq] * unet[o,i,l]
    // acc[j][0]={p0k0,p0k1} acc[j][1]={p0k2,p1k0} acc[j][2]={p1k1,p1k2}
    const float2* b2p = (const float2*)(b2 + C0 + 6 * tx);
    float2 q0 = b2p[0], q1 = b2p[1], q2 = b2p[2];
    float br[6] = { q0.x, q0.y, q1.x,   q1.y, q2.x, q2.y };

    #pragma unroll
    for (int j = 0; j < 8; ++j) {
        int r  = R0 + ty * 8 + j;
        int o  = ((r >> 4) << 7) + pt;               // h*128 + oc
        int i0 = ((r & 15) << 7) + 2 * tx;           // kc*128 + ic (even)
        size_t base = (size_t)o * 2048 + i0;
        const float2* up = (const float2*)(unet + base * 3);
        float2 u0 = up[0], u1 = up[1], u2 = up[2];
        float ua[6] = { u0.x, u0.y, u1.x,   u1.y, u2.x, u2.y };
        float2 A0 = unpack2(acc[j][0]);
        float2 A1 = unpack2(acc[j][1]);
        float2 A2 = unpack2(acc[j][2]);
        float e[6] = { A0.x + br[0], A0.y + br[1], A1.x + br[2],
                       A1.y + br[3], A2.x + br[4], A2.y + br[5] };
        // e[0..2] = (pair p0, kw 0..2), e[3..5] = (pair p0+1, kw 0..2)
        float w[18];
        #pragma unroll
        for (int kq = 0; kq < 3; ++kq) {
            #pragma unroll
            for (int l = 0; l < 3; ++l) {
                w[kq * 3 + l]     = e[kq]     * ua[l];
                w[9 + kq * 3 + l] = e[3 + kq] * ua[3 + l];
            }
        }
        float2* dst = (float2*)(out + base * 9);
        #pragma unroll
        for (int q = 0; q < 9; ++q) dst[q] = make_float2(w[2 * q], w[2 * q + 1]);
    }
}

extern "C" void kernel_launch(void* const* d_in, const int* in_sizes, int n_in,
                              void* d_out, int out_size) {
    const float* Z      = (const float*)d_in[0];
    const float* z_bias = (const float*)d_in[1];
    const float* unet_w = (const float*)d_in[2];
    const float* unet_b = (const float*)d_in[3];
    const float* pde    = (const float*)d_in[4];
    const float* W1     = (const float*)d_in[5];
    const float* U1     = (const float*)d_in[6];
    const float* b1     = (const float*)d_in[7];
    const float* W2     = (const float*)d_in[8];
    const float* b2     = (const float*)d_in[9];
    float* out = (float*)d_out;

    static int smem_set = 0;
    if (!smem_set) {
        cudaFuncSetAttribute(k_main, cudaFuncAttributeMaxDynamicSharedMemorySize,
                             3 * BSTAGE * 4 + 3 * 16 * 32 * 8);
        smem_set = 1;
    }

    k_mean<<<16, 256>>>(pde);
    k_prep<<<1, 256>>>(U1, b1, z_bias, unet_w ? unet_b : unet_b, out);
    k_hidden<<<256, 256>>>(Z, W1);
    k_main<<<dim3(8, 128), 256, 3 * BSTAGE * 4 + 3 * 16 * 32 * 8>>>(W2, b2, unet_w, out);
}

// round 4
// speedup vs baseline: 1.5984x; 1.5194x over previous
#include <cuda_runtime.h>
#include <cstdint>

#define NCOL  49152                    // OC*IC*KW
#define W2D_ELEMS 37748736ULL          // 2048*2048*3*3

// ---- scratch ----
__device__ float g_part[16 * 64];
__device__ float g_pf[256];
__device__ __align__(16) float g_hidP[256 * 256];   // hidden, mma-fragment-packed, tf32-rounded

// ---- helpers ----
__device__ __forceinline__ void cp16(void* dst_smem, const void* src) {
    unsigned u = (unsigned)__cvta_generic_to_shared(dst_smem);
    asm volatile("cp.async.cg.shared.global [%0],[%1],16;" :: "r"(u), "l"(src));
}
#define CP_COMMIT() asm volatile("cp.async.commit_group;")
#define CP_WAIT1()  asm volatile("cp.async.wait_group 1;")

__device__ __forceinline__ uint32_t to_tf32(float f) {
    uint32_t u; asm("cvt.rna.tf32.f32 %0,%1;" : "=r"(u) : "f"(f)); return u;
}
#define MMA_TF32(d, a0, a1, a2, a3, b0, b1)                                   \
    asm volatile("mma.sync.aligned.m16n8k8.row.col.f32.tf32.tf32.f32 "        \
        "{%0,%1,%2,%3},{%4,%5,%6,%7},{%8,%9},{%0,%1,%2,%3};"                  \
        : "+f"((d)[0]), "+f"((d)[1]), "+f"((d)[2]), "+f"((d)[3])              \
        : "r"(a0), "r"(a1), "r"(a2), "r"(a3), "r"(b0), "r"(b1))

// ================= prolog kernels =================
__global__ void k_mean(const float* __restrict__ pde) {
    __shared__ float sm[256];
    int b = blockIdx.x, t = threadIdx.x;
    int d = t & 63, sl = t >> 6;
    float s = 0.f;
    #pragma unroll
    for (int it = 0; it < 16; ++it) s += pde[(b * 64 + sl + it * 4) * 64 + d];
    sm[t] = s;
    __syncthreads();
    if (t < 64) g_part[b * 64 + t] = sm[t] + sm[t + 64] + sm[t + 128] + sm[t + 192];
}

__global__ void k_prep(const float* __restrict__ U1, const float* __restrict__ b1,
                       const float* __restrict__ z_bias, const float* __restrict__ u_bias,
                       float* __restrict__ out) {
    __shared__ float mean[64];
    int t = threadIdx.x;
    if (t < 64) {
        float s = 0.f;
        #pragma unroll
        for (int b = 0; b < 16; ++b) s += g_part[b * 64 + t];
        mean[t] = s * (1.0f / 1024.0f);
    }
    __syncthreads();
    float acc = b1[t];
    #pragma unroll 8
    for (int d = 0; d < 64; ++d) acc += mean[d] * U1[d * 256 + t];
    g_pf[t] = acc;
    #pragma unroll
    for (int e = 0; e < 8; ++e) {
        int o = e * 256 + t;
        out[W2D_ELEMS + o] = z_bias[o] + u_bias[o];
    }
}

// hidden = tanh(Z@W1 + pf), RNA-rounded to tf32, stored in m16n8k8 A-fragment order:
// idx = (((rt*8+mt)*32+ks)*32 + lane)*4 + j
// where r = rt*128 + mt*16 + mr, mr = (j&1)*8 + (lane>>2); k = ks*8 + (lane&3) + ((j>>1)*4)
__global__ void k_hidden(const float* __restrict__ Z, const float* __restrict__ W1) {
    __shared__ float zs[64];
    int r = blockIdx.x, t = threadIdx.x;          // t = k
    if (t < 64) zs[t] = Z[r * 64 + t];
    __syncthreads();
    float acc = g_pf[t];
    #pragma unroll 8
    for (int d = 0; d < 64; ++d) acc += zs[d] * W1[d * 256 + t];
    uint32_t tf = to_tf32(tanhf(acc));
    int rt = r >> 7, m = r & 127, mt = m >> 4, mr = m & 15;
    int g = mr & 7, jb0 = mr >> 3;
    int q = t & 3, jb1 = (t >> 2) & 1, ks = t >> 3;
    int lane = g * 4 + q, j = jb0 + 2 * jb1;
    g_hidP[(((rt * 8 + mt) * 32 + ks) * 32 + lane) * 4 + j] = __uint_as_float(tf);
}

// ================= main fused GEMM kernel (mma.sync tf32) =================
// CTA: 256 thr = 8 warps (wm = wid&3 row-quarter, wn = wid>>2 col-half).
// CTA tile M=128 x 96 raw cols; warp tile 32 x 48 = 2 m16 x 6 n8 fragments.
// K = 256 in 8 chunks of 32 (4 k-steps). B triple-buffered cp.async.
#define BSTRIDE 104                   // 96 + 8 pad floats (conflict-free b-frag LDS)
#define BSTAGE  (32 * BSTRIDE)        // 3328 floats

__global__ __launch_bounds__(256, 2) void k_tc(const float* __restrict__ W2,
                                               const float* __restrict__ b2,
                                               const float* __restrict__ unet,
                                               float* __restrict__ out) {
    __shared__ float Bsm[3 * BSTAGE];

    int tid  = threadIdx.x;
    int lane = tid & 31, wid = tid >> 5;
    int wm = wid & 3, wn = wid >> 2;
    int rt = blockIdx.x;               // 0..1
    int ct = blockIdx.y;               // 0..511

    float acc[2][6][4];
    #pragma unroll
    for (int tt = 0; tt < 2; ++tt)
        #pragma unroll
        for (int u = 0; u < 6; ++u)
            #pragma unroll
            for (int e = 0; e < 4; ++e) acc[tt][u][e] = 0.f;

    // b2 fragment columns: cols wn*48 + u*8 + 2q (+1)
    float b2r[12];
    {
        const float* bp = b2 + ct * 96 + wn * 48 + 2 * (lane & 3);
        #pragma unroll
        for (int u = 0; u < 6; ++u) {
            float2 t = *(const float2*)(bp + u * 8);
            b2r[2 * u] = t.x; b2r[2 * u + 1] = t.y;
        }
    }

    auto pf = [&](int c) {
        const float* src = W2 + (size_t)(c * 32) * NCOL + (size_t)ct * 96;
        float* dst = Bsm + (c % 3) * BSTAGE;
        #pragma unroll
        for (int i = 0; i < 3; ++i) {
            int idx = i * 256 + tid;            // 0..767 float4s
            int row = idx / 24, c4 = idx - row * 24;
            cp16(dst + row * BSTRIDE + c4 * 4, src + (size_t)row * NCOL + c4 * 4);
        }
    };

    pf(0); CP_COMMIT();
    pf(1); CP_COMMIT();

    const float* aBase0 = g_hidP + (size_t)(rt * 8 + wm * 2)     * 32 * 128;
    const float* aBase1 = g_hidP + (size_t)(rt * 8 + wm * 2 + 1) * 32 * 128;

    #pragma unroll 1
    for (int c = 0; c < 8; ++c) {
        CP_WAIT1();
        __syncthreads();
        const float* buf = Bsm + (c % 3) * BSTAGE;
        #pragma unroll
        for (int ks = 0; ks < 4; ++ks) {
            int kk = c * 4 + ks;
            float4 fa0 = *(const float4*)(aBase0 + (kk * 32 + lane) * 4);
            float4 fa1 = *(const float4*)(aBase1 + (kk * 32 + lane) * 4);
            const float* bk0 = buf + (ks * 8 + (lane & 3)) * BSTRIDE + wn * 48 + (lane >> 2);
            const float* bk1 = bk0 + 4 * BSTRIDE;
            uint32_t br0[6], br1[6];
            #pragma unroll
            for (int u = 0; u < 6; ++u) {
                br0[u] = to_tf32(bk0[u * 8]);
                br1[u] = to_tf32(bk1[u * 8]);
            }
            uint32_t a00 = __float_as_uint(fa0.x), a01 = __float_as_uint(fa0.y),
                     a02 = __float_as_uint(fa0.z), a03 = __float_as_uint(fa0.w);
            uint32_t a10 = __float_as_uint(fa1.x), a11 = __float_as_uint(fa1.y),
                     a12 = __float_as_uint(fa1.z), a13 = __float_as_uint(fa1.w);
            #pragma unroll
            for (int u = 0; u < 6; ++u) {
                MMA_TF32(acc[0][u], a00, a01, a02, a03, br0[u], br1[u]);
                MMA_TF32(acc[1][u], a10, a11, a12, a13, br0[u], br1[u]);
            }
        }
        if (c + 2 < 8) pf(c + 2);
        CP_COMMIT();
    }

    // ---- epilogue: per-warp smem staging (aliases B stage 0 region, proven disjoint
    // from the last two live B buffers), then contiguous STG.128 expansion.
    float* stg = Bsm + wid * 400;      // 8 rows x 50 floats per warp (12.8 KB < stage 0)
    int g = lane >> 2, q = lane & 3;

    #pragma unroll
    for (int rg = 0; rg < 4; ++rg) {
        int tt = rg >> 1, hi = rg & 1;
        #pragma unroll
        for (int u = 0; u < 6; ++u) {
            float2 e;
            e.x = acc[tt][u][hi * 2 + 0] + b2r[2 * u];
            e.y = acc[tt][u][hi * 2 + 1] + b2r[2 * u + 1];
            *(float2*)&stg[g * 50 + u * 8 + 2 * q] = e;
        }
        __syncwarp();

        int r0 = rt * 128 + wm * 32 + rg * 8;
        #pragma unroll 1
        for (int it = 0; it < 9; ++it) {
            int v = it * 32 + lane;             // 0..287 float4s (8 rows x 36)
            int row8 = v / 36;
            int j0 = (v - row8 * 36) * 4;       // 0..140
            int r = r0 + row8;
            int o  = ((r >> 4) << 7) + (ct >> 2);
            int i0 = ((r & 15) << 7) + ((ct & 3) << 5) + wn * 16;
            size_t nbase = (size_t)o * 2048 + i0;
            const float* urow = unet + nbase * 3;
            float res[4];
            #pragma unroll
            for (int e = 0; e < 4; ++e) {
                int j = j0 + e;
                int p = j / 9, rem = j - p * 9;
                int kq = rem / 3, l = rem - kq * 3;
                res[e] = stg[row8 * 50 + 3 * p + kq] * urow[3 * p + l];
            }
            *(float4*)(out + nbase * 9 + j0) = make_float4(res[0], res[1], res[2], res[3]);
        }
        __syncwarp();
    }
}

extern "C" void kernel_launch(void* const* d_in, const int* in_sizes, int n_in,
                              void* d_out, int out_size) {
    const float* Z      = (const float*)d_in[0];
    const float* z_bias = (const float*)d_in[1];
    const float* unet_w = (const float*)d_in[2];
    const float* unet_b = (const float*)d_in[3];
    const float* pde    = (const float*)d_in[4];
    const float* W1     = (const float*)d_in[5];
    const float* U1     = (const float*)d_in[6];
    const float* b1     = (const float*)d_in[7];
    const float* W2     = (const float*)d_in[8];
    const float* b2     = (const float*)d_in[9];
    float* out = (float*)d_out;

    k_mean<<<16, 256>>>(pde);
    k_prep<<<1, 256>>>(U1, b1, z_bias, unet_b, out);
    k_hidden<<<256, 256>>>(Z, W1);
    k_tc<<<dim3(2, 512), 256>>>(W2, b2, unet_w, out);
}

// round 5
// speedup vs baseline: 2.0174x; 1.2621x over previous
#include <cuda_runtime.h>
#include <cstdint>

#define NCOL  49152                    // OC*IC*KW
#define W2D_ELEMS 37748736ULL          // 2048*2048*3*3
#define GRID  296                      // 2 CTAs/SM persistent
#define NTILES 1024

// ---- scratch ----
__device__ float g_pf[256];
__device__ __align__(16) float g_hidP[256 * 256];   // hidden, mma-A-fragment packed, tf32-rounded

// ---- helpers ----
__device__ __forceinline__ void cp16(void* dst_smem, const void* src) {
    unsigned u = (unsigned)__cvta_generic_to_shared(dst_smem);
    asm volatile("cp.async.cg.shared.global [%0],[%1],16;" :: "r"(u), "l"(src));
}
#define CP_COMMIT() asm volatile("cp.async.commit_group;")
#define CP_WAIT1()  asm volatile("cp.async.wait_group 1;")

__device__ __forceinline__ uint32_t to_tf32(float f) {
    uint32_t u; asm("cvt.rna.tf32.f32 %0,%1;" : "=r"(u) : "f"(f)); return u;
}
#define MMA_TF32(d, a0, a1, a2, a3, b0, b1)                                   \
    asm volatile("mma.sync.aligned.m16n8k8.row.col.f32.tf32.tf32.f32 "        \
        "{%0,%1,%2,%3},{%4,%5,%6,%7},{%8,%9},{%0,%1,%2,%3};"                  \
        : "+f"((d)[0]), "+f"((d)[1]), "+f"((d)[2]), "+f"((d)[3])              \
        : "r"(a0), "r"(a1), "r"(a2), "r"(a3), "r"(b0), "r"(b1))

// ================= prolog kernels =================
// fused: pde mean -> pde_feat + b1 ; bb tail of output
__global__ void k_prep(const float* __restrict__ pde, const float* __restrict__ U1,
                       const float* __restrict__ b1, const float* __restrict__ z_bias,
                       const float* __restrict__ u_bias, float* __restrict__ out) {
    __shared__ float sm[256];
    __shared__ float mean[64];
    int t = threadIdx.x;
    int d = t & 63, sl = t >> 6;
    float s = 0.f;
    #pragma unroll 8
    for (int n = sl; n < 1024; n += 4) s += pde[n * 64 + d];
    sm[t] = s;
    __syncthreads();
    if (t < 64) mean[t] = (sm[t] + sm[t + 64] + sm[t + 128] + sm[t + 192]) * (1.0f / 1024.0f);
    __syncthreads();
    float acc = b1[t];
    #pragma unroll 8
    for (int dd = 0; dd < 64; ++dd) acc += mean[dd] * U1[dd * 256 + t];
    g_pf[t] = acc;
    #pragma unroll
    for (int e = 0; e < 8; ++e) {
        int o = e * 256 + t;
        out[W2D_ELEMS + o] = z_bias[o] + u_bias[o];
    }
}

// hidden = tanh(Z@W1 + pf), RNA-rounded tf32, stored in m16n8k8 A-fragment order
__global__ void k_hidden(const float* __restrict__ Z, const float* __restrict__ W1) {
    __shared__ float zs[64];
    int r = blockIdx.x, t = threadIdx.x;          // t = k
    if (t < 64) zs[t] = Z[r * 64 + t];
    __syncthreads();
    float acc = g_pf[t];
    #pragma unroll 8
    for (int d = 0; d < 64; ++d) acc += zs[d] * W1[d * 256 + t];
    uint32_t tf = to_tf32(tanhf(acc));
    int rt = r >> 7, m = r & 127, mt = m >> 4, mr = m & 15;
    int g = mr & 7, jb0 = mr >> 3;
    int q = t & 3, jb1 = (t >> 2) & 1, ks = t >> 3;
    int lane = g * 4 + q, j = jb0 + 2 * jb1;
    g_hidP[(((rt * 8 + mt) * 32 + ks) * 32 + lane) * 4 + j] = __uint_as_float(tf);
}

// ================= persistent fused GEMM kernel =================
// CTA: 256 thr = 8 warps (wm row-quarter, wn col-half); CTA tile 128 x 96 raw cols.
// Persistent over tiles (stride GRID); continuous cross-tile cp.async stream.
#define BSTRIDE 104                   // 96 + 8 pad (conflict-free b LDS)
#define BSTAGE  (32 * BSTRIDE)        // 3328 floats
#define STG_STRIDE 56                 // staging row stride (STS conflict-free)
#define SMEM_BYTES ((3 * BSTAGE + 8 * 8 * STG_STRIDE) * 4)

__global__ __launch_bounds__(256, 2) void k_tc(const float* __restrict__ W2,
                                               const float* __restrict__ b2,
                                               const float* __restrict__ unet,
                                               float* __restrict__ out) {
    extern __shared__ float smem[];
    float* Bsm = smem;
    int tid  = threadIdx.x;
    int lane = tid & 31, wid = tid >> 5;
    int wm = wid & 3, wn = wid >> 2;
    float* stgW = smem + 3 * BSTAGE + wid * (8 * STG_STRIDE);
    int row8 = lane >> 2, seg = lane & 3;        // epilogue roles
    int g = row8, q = seg;                        // fragment roles (same decomposition)

    int t0 = blockIdx.x;
    int rt = t0 & 1;                              // constant for this CTA (GRID even)
    const float* aB0 = g_hidP + (size_t)(rt * 8 + wm * 2) * 4096;
    const float* aB1 = aB0 + 4096;

    auto pf = [&](int nt, int c, int st) {
        const float* src = W2 + (size_t)(c * 32) * NCOL + (size_t)(nt >> 1) * 96;
        float* dst = Bsm + st * BSTAGE;
        #pragma unroll
        for (int i = 0; i < 3; ++i) {
            int idx = i * 256 + tid;            // 0..767 float4s: 32 rows x 24
            int row = idx / 24, c4 = idx - row * 24;
            cp16(dst + row * BSTRIDE + c4 * 4, src + (size_t)row * NCOL + c4 * 4);
        }
    };

    pf(t0, 0, 0); CP_COMMIT();
    pf(t0, 1, 1); CP_COMMIT();
    int stw = 2, strd = 0;

    #pragma unroll 1
    for (int tile = t0; tile < NTILES; tile += GRID) {
        int ct = tile >> 1;
        float acc[2][6][4];
        #pragma unroll
        for (int tt = 0; tt < 2; ++tt)
            #pragma unroll
            for (int u = 0; u < 6; ++u)
                #pragma unroll
                for (int e = 0; e < 4; ++e) acc[tt][u][e] = 0.f;

        #pragma unroll 1
        for (int c = 0; c < 8; ++c) {
            CP_WAIT1();
            __syncthreads();
            // continuous prefetch stream (crosses into next tile at c>=6)
            int nt = tile, nc = c + 2;
            if (nc >= 8) { nt += GRID; nc -= 8; }
            if (nt < NTILES) pf(nt, nc, stw);
            CP_COMMIT();
            stw = (stw == 2) ? 0 : stw + 1;

            const float* buf = Bsm + strd * BSTAGE;
            #pragma unroll
            for (int ks = 0; ks < 4; ++ks) {
                int kk = c * 4 + ks;
                float4 fa0 = *(const float4*)(aB0 + (size_t)(kk * 32 + lane) * 4);
                float4 fa1 = *(const float4*)(aB1 + (size_t)(kk * 32 + lane) * 4);
                const float* bk0 = buf + (ks * 8 + q) * BSTRIDE + wn * 48 + g;
                const float* bk1 = bk0 + 4 * BSTRIDE;
                uint32_t br0[6], br1[6];
                #pragma unroll
                for (int u = 0; u < 6; ++u) {
                    br0[u] = __float_as_uint(bk0[u * 8]);   // raw fp32 -> HW tf32 truncation
                    br1[u] = __float_as_uint(bk1[u * 8]);
                }
                uint32_t a00 = __float_as_uint(fa0.x), a01 = __float_as_uint(fa0.y),
                         a02 = __float_as_uint(fa0.z), a03 = __float_as_uint(fa0.w);
                uint32_t a10 = __float_as_uint(fa1.x), a11 = __float_as_uint(fa1.y),
                         a12 = __float_as_uint(fa1.z), a13 = __float_as_uint(fa1.w);
                #pragma unroll
                for (int u = 0; u < 6; ++u) {
                    MMA_TF32(acc[0][u], a00, a01, a02, a03, br0[u], br1[u]);
                    MMA_TF32(acc[1][u], a10, a11, a12, a13, br0[u], br1[u]);
                }
            }
            strd = (strd == 2) ? 0 : strd + 1;
        }

        // ---------- epilogue (per-warp, fully static indexing) ----------
        float b2r[12];
        {
            const float* bp = b2 + ct * 96 + wn * 48 + 2 * q;
            #pragma unroll
            for (int u = 0; u < 6; ++u) {
                float2 tv = *(const float2*)(bp + u * 8);
                b2r[2 * u] = tv.x; b2r[2 * u + 1] = tv.y;
            }
        }
        // per-rg output coordinates
        auto coords = [&](int rg, const float4*& up, float4*& op) {
            int r = rt * 128 + wm * 32 + rg * 8 + row8;
            int o  = ((r >> 4) << 7) + (ct >> 2);
            int i0 = ((r & 15) << 7) + ((ct & 3) << 5) + wn * 16;
            size_t nbase = (size_t)o * 2048 + i0;
            up = (const float4*)(unet + nbase * 3 + seg * 12);
            op = (float4*)(out + nbase * 9 + (size_t)seg * 36);
        };
        const float4* up; float4* op;
        coords(0, up, op);
        float4 u0 = up[0], u1 = up[1], u2 = up[2];

        #pragma unroll
        for (int rg = 0; rg < 4; ++rg) {
            int tt = rg >> 1, hi = rg & 1;
            #pragma unroll
            for (int u = 0; u < 6; ++u) {
                float2 e;
                e.x = acc[tt][u][hi * 2 + 0] + b2r[2 * u];
                e.y = acc[tt][u][hi * 2 + 1] + b2r[2 * u + 1];
                *(float2*)&stgW[g * STG_STRIDE + u * 8 + 2 * q] = e;
            }
            __syncwarp();
            float4 s0 = *(const float4*)&stgW[row8 * STG_STRIDE + seg * 12 + 0];
            float4 s1 = *(const float4*)&stgW[row8 * STG_STRIDE + seg * 12 + 4];
            float4 s2 = *(const float4*)&stgW[row8 * STG_STRIDE + seg * 12 + 8];
            // prefetch next rg's unet + advance pointers
            const float4* upn; float4* opn;
            float4 n0, n1, n2;
            if (rg < 3) {
                coords(rg + 1, upn, opn);
                n0 = upn[0]; n1 = upn[1]; n2 = upn[2];
            }
            float sv[12] = { s0.x, s0.y, s0.z, s0.w, s1.x, s1.y, s1.z, s1.w,
                             s2.x, s2.y, s2.z, s2.w };
            float uv[12] = { u0.x, u0.y, u0.z, u0.w, u1.x, u1.y, u1.z, u1.w,
                             u2.x, u2.y, u2.z, u2.w };
            #pragma unroll
            for (int jj = 0; jj < 9; ++jj) {
                float v[4];
                #pragma unroll
                for (int e = 0; e < 4; ++e) {
                    int j = jj * 4 + e;
                    int p = j / 9, rem = j - p * 9;
                    int kq = rem / 3, l = rem - kq * 3;
                    v[e] = sv[p * 3 + kq] * uv[p * 3 + l];
                }
                op[jj] = make_float4(v[0], v[1], v[2], v[3]);
            }
            if (rg < 3) { u0 = n0; u1 = n1; u2 = n2; op = opn; }
            __syncwarp();
        }
    }
}

extern "C" void kernel_launch(void* const* d_in, const int* in_sizes, int n_in,
                              void* d_out, int out_size) {
    const float* Z      = (const float*)d_in[0];
    const float* z_bias = (const float*)d_in[1];
    const float* unet_w = (const float*)d_in[2];
    const float* unet_b = (const float*)d_in[3];
    const float* pde    = (const float*)d_in[4];
    const float* W1     = (const float*)d_in[5];
    const float* U1     = (const float*)d_in[6];
    const float* b1     = (const float*)d_in[7];
    const float* W2     = (const float*)d_in[8];
    const float* b2     = (const float*)d_in[9];
    float* out = (float*)d_out;

    cudaFuncSetAttribute(k_tc, cudaFuncAttributeMaxDynamicSharedMemorySize, SMEM_BYTES);

    k_prep<<<1, 256>>>(pde, U1, b1, z_bias, unet_b, out);
    k_hidden<<<256, 256>>>(Z, W1);
    k_tc<<<GRID, 256, SMEM_BYTES>>>(W2, b2, unet_w, out);
}

// round 6
// speedup vs baseline: 2.3532x; 1.1665x over previous
#include <cuda_runtime.h>
#include <cstdint>

#define NCOL  49152                    // OC*IC*KW
#define W2D_ELEMS 37748736ULL          // 2048*2048*3*3
#define GRID  296                      // 2 CTAs/SM persistent
#define NTILES 1024

// ---- scratch ----
__device__ float g_part[64 * 64];
__device__ __align__(16) float g_hidP[256 * 256];   // hidden, mma-A-fragment packed, tf32-rounded

// ---- helpers ----
__device__ __forceinline__ void cp16(void* dst_smem, const void* src) {
    unsigned u = (unsigned)__cvta_generic_to_shared(dst_smem);
    asm volatile("cp.async.cg.shared.global [%0],[%1],16;" :: "r"(u), "l"(src));
}
#define CP_COMMIT() asm volatile("cp.async.commit_group;")
#define CP_WAIT1()  asm volatile("cp.async.wait_group 1;")

__device__ __forceinline__ uint32_t to_tf32(float f) {
    uint32_t u; asm("cvt.rna.tf32.f32 %0,%1;" : "=r"(u) : "f"(f)); return u;
}
#define MMA_TF32(d, a0, a1, a2, a3, b0, b1)                                   \
    asm volatile("mma.sync.aligned.m16n8k8.row.col.f32.tf32.tf32.f32 "        \
        "{%0,%1,%2,%3},{%4,%5,%6,%7},{%8,%9},{%0,%1,%2,%3};"                  \
        : "+f"((d)[0]), "+f"((d)[1]), "+f"((d)[2]), "+f"((d)[3])              \
        : "r"(a0), "r"(a1), "r"(a2), "r"(a3), "r"(b0), "r"(b1))

// ================= prolog kernels =================
// 64 blocks: partial pde column sums (16 rows each); blocks 64..71: bb tail.
__global__ void k_mean(const float* __restrict__ pde, const float* __restrict__ z_bias,
                       const float* __restrict__ u_bias, float* __restrict__ out) {
    int b = blockIdx.x, t = threadIdx.x;
    if (b >= 64) {
        int o = (b - 64) * 256 + t;
        out[W2D_ELEMS + o] = z_bias[o] + u_bias[o];
        return;
    }
    __shared__ float sm[256];
    int d = t & 63, sl = t >> 6;
    float s = 0.f;
    #pragma unroll
    for (int it = 0; it < 4; ++it) s += pde[(b * 16 + sl + it * 4) * 64 + d];
    sm[t] = s;
    __syncthreads();
    if (t < 64) g_part[b * 64 + t] = sm[t] + sm[t + 64] + sm[t + 128] + sm[t + 192];
}

// One block per r: mean-combine + pde_feat + hidden = tanh(Z@W1 + pde_feat + b1),
// RNA-rounded tf32, stored in m16n8k8 A-fragment order.
__global__ void k_hid(const float* __restrict__ Z, const float* __restrict__ W1,
                      const float* __restrict__ U1, const float* __restrict__ b1) {
    __shared__ float mean[64];
    __shared__ float zs[64];
    int r = blockIdx.x, t = threadIdx.x;          // t = k (output dim)
    if (t < 64) {
        float s = 0.f;
        #pragma unroll
        for (int b = 0; b < 64; ++b) s += g_part[b * 64 + t];
        mean[t] = s * (1.0f / 1024.0f);
        zs[t] = Z[r * 64 + t];
    }
    __syncthreads();
    float acc = b1[t];
    #pragma unroll 8
    for (int d = 0; d < 64; ++d)
        acc += mean[d] * U1[d * 256 + t] + zs[d] * W1[d * 256 + t];
    uint32_t tf = to_tf32(tanhf(acc));
    int rt = r >> 7, m = r & 127, mt = m >> 4, mr = m & 15;
    int g = mr & 7, jb0 = mr >> 3;
    int q = t & 3, jb1 = (t >> 2) & 1, ks = t >> 3;
    int lane = g * 4 + q, j = jb0 + 2 * jb1;
    g_hidP[(((rt * 8 + mt) * 32 + ks) * 32 + lane) * 4 + j] = __uint_as_float(tf);
}

// ================= persistent fused GEMM kernel =================
// CTA: 256 thr = 8 warps (wm row-quarter, wn col-half); CTA tile 128 x 96 raw cols.
// Persistent over tiles (stride GRID); continuous cross-tile cp.async stream.
#define BSTRIDE 104                   // 96 + 8 pad (conflict-free b LDS)
#define BSTAGE  (32 * BSTRIDE)        // 3328 floats
#define STG_STRIDE 56                 // staging row stride (STS conflict-free)
#define SMEM_BYTES ((3 * BSTAGE + 8 * 8 * STG_STRIDE) * 4)

__global__ __launch_bounds__(256, 2) void k_tc(const float* __restrict__ W2,
                                               const float* __restrict__ b2,
                                               const float* __restrict__ unet,
                                               float* __restrict__ out) {
    extern __shared__ float smem[];
    float* Bsm = smem;
    int tid  = threadIdx.x;
    int lane = tid & 31, wid = tid >> 5;
    int wm = wid & 3, wn = wid >> 2;
    float* stgW = smem + 3 * BSTAGE + wid * (8 * STG_STRIDE);
    int row8 = lane >> 2, seg = lane & 3;        // epilogue roles
    int g = row8, q = seg;                        // fragment roles

    int t0 = blockIdx.x;
    int rt = t0 & 1;                              // constant per CTA (GRID even)
    const float* aB0 = g_hidP + (size_t)(rt * 8 + wm * 2) * 4096;
    const float* aB1 = aB0 + 4096;

    auto pf = [&](int nt, int c, int st) {
        const float* src = W2 + (size_t)(c * 32) * NCOL + (size_t)(nt >> 1) * 96;
        float* dst = Bsm + st * BSTAGE;
        #pragma unroll
        for (int i = 0; i < 3; ++i) {
            int idx = i * 256 + tid;            // 0..767 float4s: 32 rows x 24
            int row = idx / 24, c4 = idx - row * 24;
            cp16(dst + row * BSTRIDE + c4 * 4, src + (size_t)row * NCOL + c4 * 4);
        }
    };

    pf(t0, 0, 0); CP_COMMIT();
    pf(t0, 1, 1); CP_COMMIT();
    int stw = 2, strd = 0;

    #pragma unroll 1
    for (int tile = t0; tile < NTILES; tile += GRID) {
        int ct = tile >> 1;
        float acc[2][6][4];
        #pragma unroll
        for (int tt = 0; tt < 2; ++tt)
            #pragma unroll
            for (int u = 0; u < 6; ++u)
                #pragma unroll
                for (int e = 0; e < 4; ++e) acc[tt][u][e] = 0.f;

        #pragma unroll 1
        for (int c = 0; c < 8; ++c) {
            CP_WAIT1();
            __syncthreads();
            int nt = tile, nc = c + 2;
            if (nc >= 8) { nt += GRID; nc -= 8; }
            if (nt < NTILES) pf(nt, nc, stw);
            CP_COMMIT();
            stw = (stw == 2) ? 0 : stw + 1;

            const float* buf = Bsm + strd * BSTAGE;
            #pragma unroll
            for (int ks = 0; ks < 4; ++ks) {
                int kk = c * 4 + ks;
                float4 fa0 = *(const float4*)(aB0 + (size_t)(kk * 32 + lane) * 4);
                float4 fa1 = *(const float4*)(aB1 + (size_t)(kk * 32 + lane) * 4);
                const float* bk0 = buf + (ks * 8 + q) * BSTRIDE + wn * 48 + g;
                const float* bk1 = bk0 + 4 * BSTRIDE;
                uint32_t br0[6], br1[6];
                #pragma unroll
                for (int u = 0; u < 6; ++u) {
                    br0[u] = __float_as_uint(bk0[u * 8]);   // raw fp32 -> HW tf32 trunc
                    br1[u] = __float_as_uint(bk1[u * 8]);
                }
                uint32_t a00 = __float_as_uint(fa0.x), a01 = __float_as_uint(fa0.y),
                         a02 = __float_as_uint(fa0.z), a03 = __float_as_uint(fa0.w);
                uint32_t a10 = __float_as_uint(fa1.x), a11 = __float_as_uint(fa1.y),
                         a12 = __float_as_uint(fa1.z), a13 = __float_as_uint(fa1.w);
                #pragma unroll
                for (int u = 0; u < 6; ++u) {
                    MMA_TF32(acc[0][u], a00, a01, a02, a03, br0[u], br1[u]);
                    MMA_TF32(acc[1][u], a10, a11, a12, a13, br0[u], br1[u]);
                }
            }
            strd = (strd == 2) ? 0 : strd + 1;
        }

        // ---------- epilogue (per-warp, fully static indexing) ----------
        float b2r[12];
        {
            const float* bp = b2 + ct * 96 + wn * 48 + 2 * q;
            #pragma unroll
            for (int u = 0; u < 6; ++u) {
                float2 tv = *(const float2*)(bp + u * 8);
                b2r[2 * u] = tv.x; b2r[2 * u + 1] = tv.y;
            }
        }
        auto coords = [&](int rg, const float4*& up, float4*& op) {
            int r = rt * 128 + wm * 32 + rg * 8 + row8;
            int o  = ((r >> 4) << 7) + (ct >> 2);
            int i0 = ((r & 15) << 7) + ((ct & 3) << 5) + wn * 16;
            size_t nbase = (size_t)o * 2048 + i0;
            up = (const float4*)(unet + nbase * 3 + seg * 12);
            op = (float4*)(out + nbase * 9 + (size_t)seg * 36);
        };
        const float4* up; float4* op;
        coords(0, up, op);
        float4 u0 = __ldcs(up), u1 = __ldcs(up + 1), u2 = __ldcs(up + 2);

        #pragma unroll
        for (int rg = 0; rg < 4; ++rg) {
            int tt = rg >> 1, hi = rg & 1;
            #pragma unroll
            for (int u = 0; u < 6; ++u) {
                float2 e;
                e.x = acc[tt][u][hi * 2 + 0] + b2r[2 * u];
                e.y = acc[tt][u][hi * 2 + 1] + b2r[2 * u + 1];
                *(float2*)&stgW[g * STG_STRIDE + u * 8 + 2 * q] = e;
            }
            __syncwarp();
            float4 s0 = *(const float4*)&stgW[row8 * STG_STRIDE + seg * 12 + 0];
            float4 s1 = *(const float4*)&stgW[row8 * STG_STRIDE + seg * 12 + 4];
            float4 s2 = *(const float4*)&stgW[row8 * STG_STRIDE + seg * 12 + 8];
            const float4* upn; float4* opn;
            float4 n0, n1, n2;
            if (rg < 3) {
                coords(rg + 1, upn, opn);
                n0 = __ldcs(upn); n1 = __ldcs(upn + 1); n2 = __ldcs(upn + 2);
            }
            float sv[12] = { s0.x, s0.y, s0.z, s0.w, s1.x, s1.y, s1.z, s1.w,
                             s2.x, s2.y, s2.z, s2.w };
            float uv[12] = { u0.x, u0.y, u0.z, u0.w, u1.x, u1.y, u1.z, u1.w,
                             u2.x, u2.y, u2.z, u2.w };
            #pragma unroll
            for (int jj = 0; jj < 9; ++jj) {
                float v[4];
                #pragma unroll
                for (int e = 0; e < 4; ++e) {
                    int j = jj * 4 + e;
                    int p = j / 9, rem = j - p * 9;
                    int kq = rem / 3, l = rem - kq * 3;
                    v[e] = sv[p * 3 + kq] * uv[p * 3 + l];
                }
                __stcs(op + jj, make_float4(v[0], v[1], v[2], v[3]));
            }
            if (rg < 3) { u0 = n0; u1 = n1; u2 = n2; op = opn; }
            __syncwarp();
        }
    }
}

extern "C" void kernel_launch(void* const* d_in, const int* in_sizes, int n_in,
                              void* d_out, int out_size) {
    const float* Z      = (const float*)d_in[0];
    const float* z_bias = (const float*)d_in[1];
    const float* unet_w = (const float*)d_in[2];
    const float* unet_b = (const float*)d_in[3];
    const float* pde    = (const float*)d_in[4];
    const float* W1     = (const float*)d_in[5];
    const float* U1     = (const float*)d_in[6];
    const float* b1     = (const float*)d_in[7];
    const float* W2     = (const float*)d_in[8];
    const float* b2     = (const float*)d_in[9];
    float* out = (float*)d_out;

    cudaFuncSetAttribute(k_tc, cudaFuncAttributeMaxDynamicSharedMemorySize, SMEM_BYTES);

    k_mean<<<72, 256>>>(pde, z_bias, unet_b, out);
    k_hid<<<256, 256>>>(Z, W1, U1, b1);
    k_tc<<<GRID, 256, SMEM_BYTES>>>(W2, b2, unet_w, out);
}